// round 9
// baseline (speedup 1.0000x reference)
#include <cuda_runtime.h>
#include <cuda_fp16.h>
#include <cstdint>
#include <cstddef>

// ---------------------------------------------------------------------------
// VenomSpmm: y = x @ (W * mask).T + bias, mask keeps k%8 in {0,2}.
// K 4096 -> 1024 packed fp16. Warp-specialized GEMM (mma.sync, fp32 accum):
//   8 consumer warps (64x64 tiles) + 2 producer warps (cp.async),
//   2-slot x 96KB mbarrier ring, BK=128 per slot (8 k-steps per handoff)
//   -> per-iteration pipeline overhead amortized over 2x the tensor work.
// ---------------------------------------------------------------------------

static constexpr int MAX_M  = 16384;
static constexpr int MAX_N  = 4096;
static constexpr int MAX_KP = 1024;

__device__ __half g_xp[(size_t)MAX_M * MAX_KP];   // 32 MB
__device__ __half g_wp[(size_t)MAX_N * MAX_KP];   // 8 MB

// ---------------------------------------------------------------------------
// Combined pack kernel: keep positions 0,2 of every 8 along K, fp32->fp16.
// First total_x groups pack x, remainder pack w.
// ---------------------------------------------------------------------------
__global__ void pack_xw(const float* __restrict__ xs, const float* __restrict__ ws,
                        long long total_x, long long total, int kd) {
    long long idx = (long long)blockIdx.x * blockDim.x + threadIdx.x;
    if (idx >= total) return;
    int gpr = kd >> 3;
    const float* src;
    __half* dst;
    long long lidx;
    if (idx < total_x) { src = xs; dst = g_xp; lidx = idx; }
    else               { src = ws; dst = g_wp; lidx = idx - total_x; }
    long long m = lidx / gpr;
    int g = (int)(lidx - m * (long long)gpr);
    const float* p = src + m * (long long)kd + ((long long)g << 3);
    __half2 h;
    h.x = __float2half(p[0]);
    h.y = __float2half(p[2]);
    *(__half2*)(dst + (size_t)m * (size_t)(kd >> 2) + 2 * (size_t)g) = h;
}

// ---------------------------------------------------------------------------
// PTX helpers (baseline ISA only — harness ptxas targets sm_103, no 'a')
// ---------------------------------------------------------------------------
__device__ __forceinline__ uint32_t smem_u32(const void* p) {
    uint32_t a;
    asm("{ .reg .u64 t; cvta.to.shared.u64 t, %1; cvt.u32.u64 %0, t; }"
        : "=r"(a) : "l"(p));
    return a;
}
__device__ __forceinline__ void cp_async16(uint32_t dst, const void* src) {
    asm volatile("cp.async.cg.shared.global [%0], [%1], 16;\n" :: "r"(dst), "l"(src));
}
__device__ __forceinline__ void mbar_init(uint32_t mbar, uint32_t cnt) {
    asm volatile("mbarrier.init.shared.b64 [%0], %1;" :: "r"(mbar), "r"(cnt) : "memory");
}
__device__ __forceinline__ void mbar_arrive(uint32_t mbar) {
    asm volatile("{ .reg .b64 t; mbarrier.arrive.shared.b64 t, [%0]; }"
                 :: "r"(mbar) : "memory");
}
__device__ __forceinline__ void cp_async_mbar_arrive_noinc(uint32_t mbar) {
    asm volatile("cp.async.mbarrier.arrive.noinc.shared.b64 [%0];"
                 :: "r"(mbar) : "memory");
}
__device__ __forceinline__ void mbar_wait(uint32_t mbar, uint32_t parity) {
    asm volatile(
        "{\n\t.reg .pred P;\n\t"
        "W%=:\n\t"
        "mbarrier.try_wait.parity.acquire.cta.shared::cta.b64 P, [%0], %1, 0x989680;\n\t"
        "@!P bra W%=;\n\t}"
        :: "r"(mbar), "r"(parity) : "memory");
}
__device__ __forceinline__ void ldsm_x4(uint32_t* r, uint32_t addr) {
    asm volatile("ldmatrix.sync.aligned.m8n8.x4.shared.b16 {%0,%1,%2,%3}, [%4];"
                 : "=r"(r[0]), "=r"(r[1]), "=r"(r[2]), "=r"(r[3]) : "r"(addr));
}
__device__ __forceinline__ void mma_fp16(float* d, const uint32_t* a, const uint32_t* b) {
    asm volatile(
        "mma.sync.aligned.m16n8k16.row.col.f32.f16.f16.f32 "
        "{%0,%1,%2,%3}, {%4,%5,%6,%7}, {%8,%9}, {%0,%1,%2,%3};\n"
        : "+f"(d[0]), "+f"(d[1]), "+f"(d[2]), "+f"(d[3])
        : "r"(a[0]), "r"(a[1]), "r"(a[2]), "r"(a[3]), "r"(b[0]), "r"(b[1]));
}
__device__ __forceinline__ uint32_t sw128(uint32_t off) {
    return off ^ ((off >> 3) & 0x70);
}

// ---------------------------------------------------------------------------
// GEMM: out[M,N] = A*B^T + bias,  A=g_xp[M,K], B=g_wp[N,K], K=1024 (fp16)
// CTA tile 128(M) x 256(N), BK=128 per slot stored as two 64-wide k-halves
// (SW128 is 128B-atom based). 2-slot mbarrier ring.
// Stage layout: A0[16K] A1[16K] B0[32K] B1[32K]  (suffix = k-half)
// Warps 0-7: consumers (2Mx4N, warp tile 64x64). Warps 8-9: producers.
// ---------------------------------------------------------------------------
static constexpr int NSTAGES     = 2;
static constexpr int AH_BYTES    = 128 * 128;          // 16 KB per A half
static constexpr int BH_BYTES    = 256 * 128;          // 32 KB per B half
static constexpr int STAGE_BYTES = 2 * AH_BYTES + 2 * BH_BYTES;  // 96 KB
static constexpr int SMEM_DYN    = NSTAGES * STAGE_BYTES;        // 192 KB
static constexpr int NTHREADS    = 320;

__global__ __launch_bounds__(NTHREADS, 1)
void gemm_fp16(const float* __restrict__ bias, float* __restrict__ out,
               int M, int N, int K) {
    extern __shared__ char smem[];
    __shared__ __align__(8) uint64_t s_mbar[2 * NSTAGES];

    const int tid = threadIdx.x;
    const int wid = tid >> 5;
    const int lane = tid & 31;
    const int m0 = blockIdx.y * 128;
    const int n0 = blockIdx.x * 256;
    const uint32_t sbase = smem_u32(smem);
    const uint32_t mb = smem_u32(&s_mbar[0]);   // full[s]  at mb + 8s
    const uint32_t me = mb + 8 * NSTAGES;       // empty[s] at me + 8s

    if (tid == 0) {
        for (int s = 0; s < NSTAGES; s++) {
            mbar_init(mb + 8 * s, 64);    // armed by 64 producer noinc-arrives
            mbar_init(me + 8 * s, 256);   // released by 256 consumer threads
        }
    }
    __syncthreads();

    const int NUM_IT = K >> 7;                  // 8 iterations of BK=128

    if (wid >= 8) {
        // ---------------- producer warps (64 threads) -----------------------
        const int pt = tid - 256;               // 0..63
        for (int it = 0; it < NUM_IT; it++) {
            const int s = it & 1;
            if (it >= 2)
                mbar_wait(me + 8 * s, (uint32_t)(((it - 2) >> 1) & 1));
            const uint32_t sb = sbase + s * STAGE_BYTES;
            const int kt = it << 7;
#pragma unroll
            for (int j = 0; j < 96; j++) {
                int cid = pt + j * 64;          // 0..6143 16B-chunks
                if (cid < 2048) {               // A: [half][128 rows][8 chunks]
                    int half = cid >> 10;
                    int w = cid & 1023;
                    int row = w >> 3;
                    int c16 = w & 7;
                    const __half* src =
                        g_xp + (size_t)(m0 + row) * K + kt + half * 64 + c16 * 8;
                    uint32_t off = (uint32_t)(row * 128 + c16 * 16);
                    cp_async16(sb + half * AH_BYTES + sw128(off), src);
                } else {                        // B: [half][256 rows][8 chunks]
                    int w = cid - 2048;         // 0..4095
                    int half = w >> 11;
                    int ww = w & 2047;
                    int row = ww >> 3;
                    int c16 = ww & 7;
                    const __half* src =
                        g_wp + (size_t)(n0 + row) * K + kt + half * 64 + c16 * 8;
                    uint32_t off = (uint32_t)(row * 128 + c16 * 16);
                    cp_async16(sb + 2 * AH_BYTES + half * BH_BYTES + sw128(off), src);
                }
            }
            cp_async_mbar_arrive_noinc(mb + 8 * s);
        }
        asm volatile("cp.async.wait_group 0;\n" ::: "memory");
        return;
    }

    // ------------------- consumer warps (256 threads) -----------------------
    const int warp_m = (wid & 1) * 64;
    const int warp_n = (wid >> 1) * 64;

    float acc[4][8][4];
#pragma unroll
    for (int i = 0; i < 4; i++)
#pragma unroll
        for (int j = 0; j < 8; j++)
#pragma unroll
            for (int r = 0; r < 4; r++) acc[i][j][r] = 0.0f;

    const int a_row = lane & 15;
    const int a_kc  = ((lane >> 4) & 1) * 8;
    const int b_row = ((lane >> 4) & 1) * 8 + (lane & 7);
    const int b_kc  = ((lane >> 3) & 1) * 8;

    for (int it = 0; it < NUM_IT; it++) {
        const int s = it & 1;
        mbar_wait(mb + 8 * s, (uint32_t)((it >> 1) & 1));

        const uint32_t sb = sbase + s * STAGE_BYTES;

#pragma unroll
        for (int ks8 = 0; ks8 < 8; ks8++) {
            const int half = ks8 >> 2;
            const int ks = ks8 & 3;
            const uint32_t sA = sb + half * AH_BYTES;
            const uint32_t sB = sb + 2 * AH_BYTES + half * BH_BYTES;

            uint32_t a[4][4], b[8][2];
#pragma unroll
            for (int mi = 0; mi < 4; mi++) {
                int row = warp_m + mi * 16 + a_row;
                uint32_t off = (uint32_t)(row * 128 + (ks * 16 + a_kc) * 2);
                ldsm_x4(a[mi], sA + sw128(off));
            }
#pragma unroll
            for (int p = 0; p < 4; p++) {
                int row = warp_n + p * 16 + b_row;
                uint32_t off = (uint32_t)(row * 128 + (ks * 16 + b_kc) * 2);
                uint32_t t[4];
                ldsm_x4(t, sB + sw128(off));
                b[p * 2 + 0][0] = t[0]; b[p * 2 + 0][1] = t[1];
                b[p * 2 + 1][0] = t[2]; b[p * 2 + 1][1] = t[3];
            }
#pragma unroll
            for (int mi = 0; mi < 4; mi++)
#pragma unroll
                for (int nj = 0; nj < 8; nj++)
                    mma_fp16(acc[mi][nj], a[mi], b[nj]);
        }

        mbar_arrive(me + 8 * s);                // release slot to producers
    }

    // ---- epilogue: bias + global writes ------------------------------------
    const int col_base = n0 + warp_n + 2 * (lane & 3);
    const int row_base = m0 + warp_m + (lane >> 2);

#pragma unroll
    for (int nj = 0; nj < 8; nj++) {
        int c = col_base + nj * 8;
        float b0 = bias[c];
        float b1 = bias[c + 1];
#pragma unroll
        for (int mi = 0; mi < 4; mi++) {
            int r = row_base + mi * 16;
            float2 v0 = make_float2(acc[mi][nj][0] + b0, acc[mi][nj][1] + b1);
            float2 v1 = make_float2(acc[mi][nj][2] + b0, acc[mi][nj][3] + b1);
            *(float2*)(out + (size_t)r * N + c) = v0;
            *(float2*)(out + (size_t)(r + 8) * N + c) = v1;
        }
    }
}

// ---------------------------------------------------------------------------
// Launch
// ---------------------------------------------------------------------------
extern "C" void kernel_launch(void* const* d_in, const int* in_sizes, int n_in,
                              void* d_out, int out_size) {
    const float* x    = (const float*)d_in[0];
    const float* w    = (const float*)d_in[1];
    const float* bias = (const float*)d_in[2];
    float* out = (float*)d_out;

    const int n_out = in_sizes[2];                        // 4096
    const int kd    = in_sizes[1] / n_out;                // 4096
    const int M     = (int)((long long)in_sizes[0] / kd); // 16384
    const int Kp    = kd / 4;                             // 1024

    cudaFuncSetAttribute(gemm_fp16,
                         cudaFuncAttributeMaxDynamicSharedMemorySize, SMEM_DYN);

    {
        long long total_x = (long long)M * (kd >> 3);
        long long total = total_x + (long long)n_out * (kd >> 3);
        pack_xw<<<(int)((total + 255) / 256), 256>>>(x, w, total_x, total, kd);
    }
    {
        dim3 grid(n_out / 256, M / 128);
        gemm_fp16<<<grid, NTHREADS, SMEM_DYN>>>(bias, out, M, n_out, Kp);
    }
}

// round 10
// speedup vs baseline: 1.1921x; 1.1921x over previous
#include <cuda_runtime.h>
#include <cuda_fp16.h>
#include <cstdint>
#include <cstddef>

// ---------------------------------------------------------------------------
// VenomSpmm: y = x @ (W * mask).T + bias, mask keeps k%8 in {0,2}.
// K 4096 -> 1024 packed fp16. Single-pass fp16 GEMM (fp32 accum) on mma.sync.
// R9 ncu: tensor pipe 52%, occupancy 14.5% -> latency-bound, not issue-bound.
// Fix: CTA tile 128x128, 3-stage x 32KB ring (96KB smem) + launch_bounds(256,2)
//      -> 2 CTAs/SM, 16 warps/SM for cross-CTA latency hiding.
// ---------------------------------------------------------------------------

static constexpr int MAX_M  = 16384;
static constexpr int MAX_N  = 4096;
static constexpr int MAX_KP = 1024;

__device__ __half g_xp[(size_t)MAX_M * MAX_KP];   // 32 MB
__device__ __half g_wp[(size_t)MAX_N * MAX_KP];   // 8 MB

// ---------------------------------------------------------------------------
// Combined pack kernel: keep positions 0,2 of every 8 along K, fp32->fp16.
// ---------------------------------------------------------------------------
__global__ void pack_xw(const float* __restrict__ xs, const float* __restrict__ ws,
                        long long total_x, long long total, int kd) {
    long long idx = (long long)blockIdx.x * blockDim.x + threadIdx.x;
    if (idx >= total) return;
    int gpr = kd >> 3;
    const float* src;
    __half* dst;
    long long lidx;
    if (idx < total_x) { src = xs; dst = g_xp; lidx = idx; }
    else               { src = ws; dst = g_wp; lidx = idx - total_x; }
    long long m = lidx / gpr;
    int g = (int)(lidx - m * (long long)gpr);
    const float* p = src + m * (long long)kd + ((long long)g << 3);
    __half2 h;
    h.x = __float2half(p[0]);
    h.y = __float2half(p[2]);
    *(__half2*)(dst + (size_t)m * (size_t)(kd >> 2) + 2 * (size_t)g) = h;
}

// ---------------------------------------------------------------------------
// PTX helpers (baseline ISA only — harness ptxas targets sm_103, no 'a')
// ---------------------------------------------------------------------------
__device__ __forceinline__ uint32_t smem_u32(const void* p) {
    uint32_t a;
    asm("{ .reg .u64 t; cvta.to.shared.u64 t, %1; cvt.u32.u64 %0, t; }"
        : "=r"(a) : "l"(p));
    return a;
}
__device__ __forceinline__ void cp_async16(uint32_t dst, const void* src) {
    asm volatile("cp.async.cg.shared.global [%0], [%1], 16;\n" :: "r"(dst), "l"(src));
}
__device__ __forceinline__ void cp_async_commit() {
    asm volatile("cp.async.commit_group;\n" ::: "memory");
}
template <int N>
__device__ __forceinline__ void cp_async_wait() {
    asm volatile("cp.async.wait_group %0;\n" :: "n"(N) : "memory");
}
__device__ __forceinline__ void ldsm_x4(uint32_t* r, uint32_t addr) {
    asm volatile("ldmatrix.sync.aligned.m8n8.x4.shared.b16 {%0,%1,%2,%3}, [%4];"
                 : "=r"(r[0]), "=r"(r[1]), "=r"(r[2]), "=r"(r[3]) : "r"(addr));
}
__device__ __forceinline__ void mma_fp16(float* d, const uint32_t* a, const uint32_t* b) {
    asm volatile(
        "mma.sync.aligned.m16n8k16.row.col.f32.f16.f16.f32 "
        "{%0,%1,%2,%3}, {%4,%5,%6,%7}, {%8,%9}, {%0,%1,%2,%3};\n"
        : "+f"(d[0]), "+f"(d[1]), "+f"(d[2]), "+f"(d[3])
        : "r"(a[0]), "r"(a[1]), "r"(a[2]), "r"(a[3]), "r"(b[0]), "r"(b[1]));
}
__device__ __forceinline__ uint32_t sw128(uint32_t off) {
    return off ^ ((off >> 3) & 0x70);
}

// ---------------------------------------------------------------------------
// GEMM: out[M,N] = A*B^T + bias,  A=g_xp[M,K], B=g_wp[N,K], K=1024 (fp16)
// CTA tile 128(M) x 128(N), BK=64 (128B rows, SW128), 3-stage cp.async ring.
// 8 warps as 2(M) x 4(N); warp tile 64x32; m16n8k16 fp16 mma, fp32 accum.
// 96 KB smem + <=128 regs -> 2 CTAs/SM.
// ---------------------------------------------------------------------------
static constexpr int NSTAGES     = 3;
static constexpr int A_BYTES     = 128 * 128;          // 16 KB
static constexpr int B_BYTES     = 128 * 128;          // 16 KB
static constexpr int STAGE_BYTES = A_BYTES + B_BYTES;  // 32 KB
static constexpr int SMEM_DYN    = NSTAGES * STAGE_BYTES;   // 96 KB

__global__ __launch_bounds__(256, 2)
void gemm_fp16(const float* __restrict__ bias, float* __restrict__ out,
               int M, int N, int K) {
    extern __shared__ char smem[];
    const int tid = threadIdx.x;
    const int wid = tid >> 5;
    const int lane = tid & 31;
    const int m0 = blockIdx.y * 128;
    const int n0 = blockIdx.x * 128;
    const uint32_t sbase = smem_u32(smem);

    const int warp_m = (wid & 1) * 64;
    const int warp_n = (wid >> 1) * 32;

    const int NUM_IT = K >> 6;                        // 16 k-tiles of 64

    // ---- async stage loader: 2048 16B-chunks over 256 threads x 8 ----------
    auto load_stage = [&](int slot, int it) {
        const uint32_t sb = sbase + slot * STAGE_BYTES;
        const int kt = it << 6;
#pragma unroll
        for (int i = 0; i < 8; i++) {
            int cid = tid + i * 256;                  // 0..2047
            int mat = cid >> 10;                      // 0:A 1:B
            int within = cid & 1023;
            int row = within >> 3;                    // 0..127
            int c16 = within & 7;
            const __half* src = (mat == 0)
                ? g_xp + (size_t)(m0 + row) * K + kt + c16 * 8
                : g_wp + (size_t)(n0 + row) * K + kt + c16 * 8;
            uint32_t off = (uint32_t)(row * 128 + c16 * 16);
            cp_async16(sb + mat * A_BYTES + sw128(off), src);
        }
        cp_async_commit();
    };

    load_stage(0, 0);
    load_stage(1, 1);

    float acc[4][4][4];
#pragma unroll
    for (int i = 0; i < 4; i++)
#pragma unroll
        for (int j = 0; j < 4; j++)
#pragma unroll
            for (int r = 0; r < 4; r++) acc[i][j][r] = 0.0f;

    const int a_row = lane & 15;
    const int a_kc  = ((lane >> 4) & 1) * 8;
    const int b_row = ((lane >> 4) & 1) * 8 + (lane & 7);
    const int b_kc  = ((lane >> 3) & 1) * 8;

    for (int it = 0; it < NUM_IT; it++) {
        const int s = it % NSTAGES;
        if (it < NUM_IT - 1) cp_async_wait<NSTAGES - 2>();
        else                 cp_async_wait<0>();
        __syncthreads();

        if (it + NSTAGES - 1 < NUM_IT)
            load_stage((it + NSTAGES - 1) % NSTAGES, it + NSTAGES - 1);

        const uint32_t sA = sbase + s * STAGE_BYTES;
        const uint32_t sB = sA + A_BYTES;

#pragma unroll
        for (int ks = 0; ks < 4; ks++) {
            uint32_t a[4][4], b[4][2];
#pragma unroll
            for (int mi = 0; mi < 4; mi++) {
                int row = warp_m + mi * 16 + a_row;
                uint32_t off = (uint32_t)(row * 128 + (ks * 16 + a_kc) * 2);
                ldsm_x4(a[mi], sA + sw128(off));
            }
#pragma unroll
            for (int p = 0; p < 2; p++) {
                int row = warp_n + p * 16 + b_row;
                uint32_t off = (uint32_t)(row * 128 + (ks * 16 + b_kc) * 2);
                uint32_t t[4];
                ldsm_x4(t, sB + sw128(off));
                b[p * 2 + 0][0] = t[0]; b[p * 2 + 0][1] = t[1];
                b[p * 2 + 1][0] = t[2]; b[p * 2 + 1][1] = t[3];
            }
#pragma unroll
            for (int mi = 0; mi < 4; mi++)
#pragma unroll
                for (int nj = 0; nj < 4; nj++)
                    mma_fp16(acc[mi][nj], a[mi], b[nj]);
        }
    }

    // ---- epilogue: bias + global writes ------------------------------------
    const int col_base = n0 + warp_n + 2 * (lane & 3);
    const int row_base = m0 + warp_m + (lane >> 2);

#pragma unroll
    for (int nj = 0; nj < 4; nj++) {
        int c = col_base + nj * 8;
        float b0 = bias[c];
        float b1 = bias[c + 1];
#pragma unroll
        for (int mi = 0; mi < 4; mi++) {
            int r = row_base + mi * 16;
            float2 v0 = make_float2(acc[mi][nj][0] + b0, acc[mi][nj][1] + b1);
            float2 v1 = make_float2(acc[mi][nj][2] + b0, acc[mi][nj][3] + b1);
            *(float2*)(out + (size_t)r * N + c) = v0;
            *(float2*)(out + (size_t)(r + 8) * N + c) = v1;
        }
    }
}

// ---------------------------------------------------------------------------
// Launch
// ---------------------------------------------------------------------------
extern "C" void kernel_launch(void* const* d_in, const int* in_sizes, int n_in,
                              void* d_out, int out_size) {
    const float* x    = (const float*)d_in[0];
    const float* w    = (const float*)d_in[1];
    const float* bias = (const float*)d_in[2];
    float* out = (float*)d_out;

    const int n_out = in_sizes[2];                        // 4096
    const int kd    = in_sizes[1] / n_out;                // 4096
    const int M     = (int)((long long)in_sizes[0] / kd); // 16384
    const int Kp    = kd / 4;                             // 1024

    cudaFuncSetAttribute(gemm_fp16,
                         cudaFuncAttributeMaxDynamicSharedMemorySize, SMEM_DYN);

    {
        long long total_x = (long long)M * (kd >> 3);
        long long total = total_x + (long long)n_out * (kd >> 3);
        pack_xw<<<(int)((total + 255) / 256), 256>>>(x, w, total_x, total, kd);
    }
    {
        dim3 grid(n_out / 128, M / 128);
        gemm_fp16<<<grid, 256, SMEM_DYN>>>(bias, out, M, n_out, Kp);
    }
}